// round 11
// baseline (speedup 1.0000x reference)
#include <cuda_runtime.h>
#include <cuda_fp16.h>
#include <cstdint>

#define NT    256
#define GRID  148
#define DTf   0.05f
#define MAXTILES 1024

// ---------------- Tsit5 tableau ----------------
__constant__ float c_A[6][5] = {
    {0.f, 0.f, 0.f, 0.f, 0.f},
    {0.161f, 0.f, 0.f, 0.f, 0.f},
    {-0.008480655492356989f, 0.335480655492357f, 0.f, 0.f, 0.f},
    {2.8971530571054935f, -6.359448489975075f, 4.3622954328695815f, 0.f, 0.f},
    {5.325864828439257f, -11.748883564062828f, 7.4955393428898365f, -0.09249506636175525f, 0.f},
    {5.86145544294642f, -12.92096931784711f, 8.159367898576159f, -0.071584973281401f, -0.028269050394068383f},
};
__constant__ float c_Bc[6] = {
    0.09646076681806523f, 0.01f, 0.4798896504144996f,
    1.379008574103742f, -3.290069515436081f, 2.324710524099774f
};

// k_1..k_5 stage derivatives, f16x2 fragments, [tile][stage][q][tid] (coalesced on tid).
__device__ uint32_t g_k[(size_t)MAXTILES * 5 * 16 * NT];

// ---------------- SMEM layout (bytes) ----------------
// B-fragments PAIRED (two consecutive-ks frags adjacent, 16B/lane -> LDS.128).
//  W1 per c (10240B): pair p(2)*nf(8)*512B, then single ks4: nf(8)*256B
//  W2 per c (32768B): pair p(8)*nf(8)*512B
//  W3 per c-chunk (8192B): pair jp(2)*nf(8)*512B
#define OW1 0          // 4 * 10240 = 40960
#define OW2 40960      // 4 * 32768 = 131072
#define OW3 172032     // 4 * 8192  = 32768
#define OB1 204800     // 256 f32
#define OB2 205824     // 256 f32
#define OB3 206848     // 64 f32
#define SMEM_BYTES 207360

// ---------------- helpers ----------------
__device__ __forceinline__ uint32_t packh(float lo, float hi) {
    uint32_t r; asm("cvt.rn.f16x2.f32 %0, %1, %2;" : "=r"(r) : "f"(hi), "f"(lo)); return r;
}
__device__ __forceinline__ float2 unpackh(uint32_t v) {
    __half2 h = *reinterpret_cast<__half2*>(&v);
    return __half22float2(h);
}
__device__ __forceinline__ float tanh_fast(float x) {
    float y; asm("tanh.approx.f32 %0, %1;" : "=f"(y) : "f"(x)); return y;
}
__device__ __forceinline__ float silu(float x) {
    float t = tanh_fast(0.5f * x);
    return fmaf(x, 0.5f * t, 0.5f * x);
}
// f16 inputs, f16 accumulate (C/D = 2 regs) — halves acc register footprint
__device__ __forceinline__ void mma_f16h(uint32_t* c, const uint32_t* a, uint32_t b0, uint32_t b1) {
    asm volatile(
        "mma.sync.aligned.m16n8k16.row.col.f16.f16.f16.f16 "
        "{%0,%1},{%2,%3,%4,%5},{%6,%7},{%0,%1};"
        : "+r"(c[0]), "+r"(c[1])
        : "r"(a[0]), "r"(a[1]), "r"(a[2]), "r"(a[3]), "r"(b0), "r"(b1));
}
// f16 inputs, f32 accumulate — used for GEMM3 (k precision)
__device__ __forceinline__ void mma_f16f(float* c, const uint32_t* a, uint32_t b0, uint32_t b1) {
    asm volatile(
        "mma.sync.aligned.m16n8k16.row.col.f32.f16.f16.f32 "
        "{%0,%1,%2,%3},{%4,%5,%6,%7},{%8,%9},{%0,%1,%2,%3};"
        : "+f"(c[0]), "+f"(c[1]), "+f"(c[2]), "+f"(c[3])
        : "r"(a[0]), "r"(a[1]), "r"(a[2]), "r"(a[3]), "r"(b0), "r"(b1));
}

// W[K][N] row-major f32 -> f16 paired B-fragment SMEM (layouts above).
template<int MODE>
__device__ void conv_w(const float* __restrict__ G, int K, int N, char* dst, int tid) {
    for (int idx = tid; idx < K * N; idx += NT) {
        int k = idx / N, n = idx - k * N;
        int lane = (n & 7) * 4 + ((k & 7) >> 1);
        int kb = (((k >> 3) & 1) << 2) + ((k & 1) << 1);   // byte offset within 8B frag
        int ks = k >> 4;
        int off;
        if (MODE == 1) {
            int c = n >> 6, nf = (n >> 3) & 7;
            if (ks < 4)
                off = c * 10240 + (ks >> 1) * 4096 + nf * 512 + lane * 16 + (ks & 1) * 8 + kb;
            else
                off = c * 10240 + 8192 + nf * 256 + lane * 8 + kb;
        } else if (MODE == 2) {
            int c = n >> 6, nf = (n >> 3) & 7;
            off = c * 32768 + ((ks >> 1) * 8 + nf) * 512 + lane * 16 + (ks & 1) * 8 + kb;
        } else {
            int nf = n >> 3, c = ks >> 2, jp = (ks >> 1) & 1;
            off = c * 8192 + (jp * 8 + nf) * 512 + lane * 16 + (ks & 1) * 8 + kb;
        }
        *(__half*)(dst + off) = __float2half(G[idx]);
    }
}

extern __shared__ char sm[];

__global__ void __launch_bounds__(NT, 1)
tsit5_mma_kernel(const float* __restrict__ obs, const float* __restrict__ act,
                 const float* __restrict__ gW1, const float* __restrict__ gb1,
                 const float* __restrict__ gW2, const float* __restrict__ gb2,
                 const float* __restrict__ gW3, const float* __restrict__ gb3,
                 float* __restrict__ out, int ntiles)
{
    const int tid = threadIdx.x;

    conv_w<1>(gW1,  80, 256, sm + OW1, tid);
    conv_w<2>(gW2, 256, 256, sm + OW2, tid);
    conv_w<3>(gW3, 256,  64, sm + OW3, tid);
    for (int i = tid; i < 256; i += NT) {
        ((float*)(sm + OB1))[i] = gb1[i];
        ((float*)(sm + OB2))[i] = gb2[i];
    }
    for (int i = tid; i < 64; i += NT) ((float*)(sm + OB3))[i] = gb3[i];
    __syncthreads();

    const float* B1 = (const float*)(sm + OB1);
    const float* B2 = (const float*)(sm + OB2);
    const float* B3 = (const float*)(sm + OB3);

    const int w  = tid >> 5, l = tid & 31;
    const int m0 = w * 16;
    const int rl = l >> 2;
    const int cp = (l & 3) * 2;

    for (int tile = blockIdx.x; tile < ntiles; tile += GRID) {
        const long rowlo = (long)tile * 128 + m0 + rl;
        const float* obs_lo = obs + rowlo * 64;
        const float* obs_hi = obs_lo + 8 * 64;
        uint32_t* kt = g_k + ((size_t)tile * 5) * 16 * NT + tid;

        // A-frags: ks 0..3 = x (rebuilt per stage), ks 4 = actions (persistent)
        uint32_t xa[5][4];
        {
            const float* act_lo = act + rowlo * 16;
            float2 v;
            v = *(const float2*)(act_lo + cp);           xa[4][0] = packh(v.x, v.y);
            v = *(const float2*)(act_lo + 128 + cp);     xa[4][1] = packh(v.x, v.y);
            v = *(const float2*)(act_lo + 8 + cp);       xa[4][2] = packh(v.x, v.y);
            v = *(const float2*)(act_lo + 128 + 8 + cp); xa[4][3] = packh(v.x, v.y);
        }

        #pragma unroll 1   // one body copy: no spills, small I$
        for (int st = 0; st < 6; st++) {
            // ---- build x_st A-frags: fp32 y0 (L2-hot) + dt * sum_j a[st][j]*k_j ----
            #pragma unroll
            for (int ks = 0; ks < 4; ks++)
                #pragma unroll
                for (int r = 0; r < 4; r++) {
                    const int q = ks * 4 + r;
                    const float* yp = ((r & 1) ? obs_hi : obs_lo) + ks * 16 + (r >> 1) * 8 + cp;
                    float2 v = *(const float2*)yp;
                    #pragma unroll
                    for (int j = 0; j < 5; j++)
                        if (j < st) {
                            float a = DTf * c_A[st][j];
                            float2 kk = unpackh(kt[(j * 16 + q) * NT]);
                            v.x = fmaf(a, kk.x, v.x);
                            v.y = fmaf(a, kk.y, v.y);
                        }
                    xa[ks][r] = packh(v.x, v.y);
                }

            // ---- GEMM1: h1 = silu(X @ W1 + b1), f16 acc -> hA frags ----
            uint32_t hA[16][4];
            #pragma unroll
            for (int c = 0; c < 4; c++) {
                const uint4* q1 = (const uint4*)(sm + OW1 + c * 10240) + l;
                const uint2* s1 = (const uint2*)(sm + OW1 + c * 10240 + 8192) + l;
                uint32_t acc[8][2];
                #pragma unroll
                for (int nf = 0; nf < 8; nf++) {
                    float2 bb = *(const float2*)(B1 + c * 64 + nf * 8 + cp);
                    uint32_t bh = packh(bb.x, bb.y);
                    acc[nf][0] = bh; acc[nf][1] = bh;
                }
                #pragma unroll
                for (int p = 0; p < 2; p++)
                    #pragma unroll
                    for (int nf = 0; nf < 8; nf++) {
                        uint4 bb = q1[(p * 8 + nf) * 32];
                        mma_f16h(acc[nf], xa[2 * p],     bb.x, bb.y);
                        mma_f16h(acc[nf], xa[2 * p + 1], bb.z, bb.w);
                    }
                #pragma unroll
                for (int nf = 0; nf < 8; nf++) {
                    uint2 bb = s1[nf * 32];
                    mma_f16h(acc[nf], xa[4], bb.x, bb.y);
                }
                #pragma unroll
                for (int nf = 0; nf < 8; nf++) {
                    float2 v0 = unpackh(acc[nf][0]);
                    float2 v1 = unpackh(acc[nf][1]);
                    hA[c * 4 + (nf >> 1)][(nf & 1) * 2 + 0] = packh(silu(v0.x), silu(v0.y));
                    hA[c * 4 + (nf >> 1)][(nf & 1) * 2 + 1] = packh(silu(v1.x), silu(v1.y));
                }
            }

            // ---- GEMM2 (f16 acc, silu) + fused GEMM3 partials (f32 acc) ----
            float acc3[8][4];
            #pragma unroll
            for (int nf = 0; nf < 8; nf++)
                acc3[nf][0] = acc3[nf][1] = acc3[nf][2] = acc3[nf][3] = 0.f;

            #pragma unroll 1
            for (int c = 0; c < 4; c++) {
                const uint4* q2 = (const uint4*)(sm + OW2 + c * 32768) + l;
                const uint4* q3 = (const uint4*)(sm + OW3 + c * 8192) + l;
                uint32_t acc[8][2];
                #pragma unroll
                for (int nf = 0; nf < 8; nf++) {
                    float2 bb = *(const float2*)(B2 + c * 64 + nf * 8 + cp);
                    uint32_t bh = packh(bb.x, bb.y);
                    acc[nf][0] = bh; acc[nf][1] = bh;
                }
                #pragma unroll
                for (int p = 0; p < 8; p++)
                    #pragma unroll
                    for (int nf = 0; nf < 8; nf++) {
                        uint4 bb = q2[(p * 8 + nf) * 32];
                        mma_f16h(acc[nf], hA[2 * p],     bb.x, bb.y);
                        mma_f16h(acc[nf], hA[2 * p + 1], bb.z, bb.w);
                    }
                uint32_t ht[4][4];
                #pragma unroll
                for (int nf = 0; nf < 8; nf++) {
                    float2 v0 = unpackh(acc[nf][0]);
                    float2 v1 = unpackh(acc[nf][1]);
                    ht[nf >> 1][(nf & 1) * 2 + 0] = packh(silu(v0.x), silu(v0.y));
                    ht[nf >> 1][(nf & 1) * 2 + 1] = packh(silu(v1.x), silu(v1.y));
                }
                #pragma unroll
                for (int jp = 0; jp < 2; jp++)
                    #pragma unroll
                    for (int nf = 0; nf < 8; nf++) {
                        uint4 bb = q3[(jp * 8 + nf) * 32];
                        mma_f16f(acc3[nf], ht[2 * jp],     bb.x, bb.y);
                        mma_f16f(acc3[nf], ht[2 * jp + 1], bb.z, bb.w);
                    }
            }

            // ---- GEMM3 epilogue: k_st = acc3 + b3 -> scratch (or final y1) ----
            if (st < 5) {
                #pragma unroll
                for (int nf = 0; nf < 8; nf++) {
                    float2 bb = *(const float2*)(B3 + nf * 8 + cp);
                    int q = (nf >> 1) * 4 + (nf & 1) * 2;
                    kt[(st * 16 + q + 0) * NT] = packh(acc3[nf][0] + bb.x, acc3[nf][1] + bb.y);
                    kt[(st * 16 + q + 1) * NT] = packh(acc3[nf][2] + bb.x, acc3[nf][3] + bb.y);
                }
            } else {
                float* o_lo = out + rowlo * 64;
                float* o_hi = o_lo + 8 * 64;
                const float d5 = DTf * c_Bc[5];
                #pragma unroll
                for (int nf = 0; nf < 8; nf++) {
                    float2 bb  = *(const float2*)(B3 + nf * 8 + cp);
                    float2 ylo = *(const float2*)(obs_lo + nf * 8 + cp);
                    float2 yhi = *(const float2*)(obs_hi + nf * 8 + cp);
                    float lo0 = fmaf(d5, acc3[nf][0] + bb.x, ylo.x);
                    float lo1 = fmaf(d5, acc3[nf][1] + bb.y, ylo.y);
                    float hi0 = fmaf(d5, acc3[nf][2] + bb.x, yhi.x);
                    float hi1 = fmaf(d5, acc3[nf][3] + bb.y, yhi.y);
                    int ql = (nf >> 1) * 4 + (nf & 1) * 2, qh = ql + 1;
                    #pragma unroll
                    for (int j = 0; j < 5; j++) {
                        float d = DTf * c_Bc[j];
                        float2 klo = unpackh(kt[(j * 16 + ql) * NT]);
                        float2 khi = unpackh(kt[(j * 16 + qh) * NT]);
                        lo0 = fmaf(d, klo.x, lo0); lo1 = fmaf(d, klo.y, lo1);
                        hi0 = fmaf(d, khi.x, hi0); hi1 = fmaf(d, khi.y, hi1);
                    }
                    *(float2*)(o_lo + nf * 8 + cp) = make_float2(lo0, lo1);
                    *(float2*)(o_hi + nf * 8 + cp) = make_float2(hi0, hi1);
                }
            }
        }
    }
}

extern "C" void kernel_launch(void* const* d_in, const int* in_sizes, int n_in,
                              void* d_out, int out_size)
{
    const float* obs = (const float*)d_in[0];
    const float* act = (const float*)d_in[1];
    const float* W1  = (const float*)d_in[2];
    const float* b1  = (const float*)d_in[3];
    const float* W2  = (const float*)d_in[4];
    const float* b2  = (const float*)d_in[5];
    const float* W3  = (const float*)d_in[6];
    const float* b3  = (const float*)d_in[7];
    float* out = (float*)d_out;

    const int batch  = in_sizes[0] / 64;
    int ntiles = batch / 128;
    if (ntiles > MAXTILES) ntiles = MAXTILES;

    cudaFuncSetAttribute(tsit5_mma_kernel,
                         cudaFuncAttributeMaxDynamicSharedMemorySize, SMEM_BYTES);

    tsit5_mma_kernel<<<GRID, NT, SMEM_BYTES>>>(obs, act, W1, b1, W2, b2, W3, b3, out, ntiles);
}

// round 12
// speedup vs baseline: 1.0085x; 1.0085x over previous
#include <cuda_runtime.h>
#include <cuda_fp16.h>
#include <cstdint>

#define NT    256
#define GRID  148
#define DTf   0.05f
#define MAXTILES 1024

// ---------------- Tsit5 tableau ----------------
__constant__ float c_A[6][5] = {
    {0.f, 0.f, 0.f, 0.f, 0.f},
    {0.161f, 0.f, 0.f, 0.f, 0.f},
    {-0.008480655492356989f, 0.335480655492357f, 0.f, 0.f, 0.f},
    {2.8971530571054935f, -6.359448489975075f, 4.3622954328695815f, 0.f, 0.f},
    {5.325864828439257f, -11.748883564062828f, 7.4955393428898365f, -0.09249506636175525f, 0.f},
    {5.86145544294642f, -12.92096931784711f, 8.159367898576159f, -0.071584973281401f, -0.028269050394068383f},
};
__constant__ float c_Bc[6] = {
    0.09646076681806523f, 0.01f, 0.4798896504144996f,
    1.379008574103742f, -3.290069515436081f, 2.324710524099774f
};

// k_1..k_5 stage derivatives, f16x2 fragments, [tile][stage][q][tid] (coalesced on tid).
__device__ uint32_t g_k[(size_t)MAXTILES * 5 * 16 * NT];

// ---------------- SMEM layout (bytes) ----------------
// B-fragments PAIRED (two consecutive-ks frags adjacent, 16B/lane -> LDS.128).
//  W1 per c (10240B): pair p(2)*nf(8)*512B, then single ks4: nf(8)*256B
//  W2 per c (32768B): pair p(8)*nf(8)*512B
//  W3 per c-chunk (8192B): pair jp(2)*nf(8)*512B
#define OW1 0          // 4 * 10240 = 40960
#define OW2 40960      // 4 * 32768 = 131072
#define OW3 172032     // 4 * 8192  = 32768
#define OB1 204800     // 256 f32
#define OB2 205824     // 256 f32
#define OB3 206848     // 64 f32
#define SMEM_BYTES 207360

// ---------------- helpers ----------------
__device__ __forceinline__ uint32_t packh(float lo, float hi) {
    uint32_t r; asm("cvt.rn.f16x2.f32 %0, %1, %2;" : "=r"(r) : "f"(hi), "f"(lo)); return r;
}
__device__ __forceinline__ float2 unpackh(uint32_t v) {
    __half2 h = *reinterpret_cast<__half2*>(&v);
    return __half22float2(h);
}
__device__ __forceinline__ float tanh_fast(float x) {
    float y; asm("tanh.approx.f32 %0, %1;" : "=f"(y) : "f"(x)); return y;
}
__device__ __forceinline__ float silu(float x) {
    float t = tanh_fast(0.5f * x);
    return fmaf(x, 0.5f * t, 0.5f * x);
}
// f16 inputs, f16 accumulate (C/D = 2 regs)
__device__ __forceinline__ void mma_f16h(uint32_t* c, const uint32_t* a, uint32_t b0, uint32_t b1) {
    asm volatile(
        "mma.sync.aligned.m16n8k16.row.col.f16.f16.f16.f16 "
        "{%0,%1},{%2,%3,%4,%5},{%6,%7},{%0,%1};"
        : "+r"(c[0]), "+r"(c[1])
        : "r"(a[0]), "r"(a[1]), "r"(a[2]), "r"(a[3]), "r"(b0), "r"(b1));
}

// W[K][N] row-major f32 -> f16 paired B-fragment SMEM (layouts above).
template<int MODE>
__device__ void conv_w(const float* __restrict__ G, int K, int N, char* dst, int tid) {
    for (int idx = tid; idx < K * N; idx += NT) {
        int k = idx / N, n = idx - k * N;
        int lane = (n & 7) * 4 + ((k & 7) >> 1);
        int kb = (((k >> 3) & 1) << 2) + ((k & 1) << 1);   // byte offset within 8B frag
        int ks = k >> 4;
        int off;
        if (MODE == 1) {
            int c = n >> 6, nf = (n >> 3) & 7;
            if (ks < 4)
                off = c * 10240 + (ks >> 1) * 4096 + nf * 512 + lane * 16 + (ks & 1) * 8 + kb;
            else
                off = c * 10240 + 8192 + nf * 256 + lane * 8 + kb;
        } else if (MODE == 2) {
            int c = n >> 6, nf = (n >> 3) & 7;
            off = c * 32768 + ((ks >> 1) * 8 + nf) * 512 + lane * 16 + (ks & 1) * 8 + kb;
        } else {
            int nf = n >> 3, c = ks >> 2, jp = (ks >> 1) & 1;
            off = c * 8192 + (jp * 8 + nf) * 512 + lane * 16 + (ks & 1) * 8 + kb;
        }
        *(__half*)(dst + off) = __float2half(G[idx]);
    }
}

extern __shared__ char sm[];

__global__ void __launch_bounds__(NT, 1)
tsit5_mma_kernel(const float* __restrict__ obs, const float* __restrict__ act,
                 const float* __restrict__ gW1, const float* __restrict__ gb1,
                 const float* __restrict__ gW2, const float* __restrict__ gb2,
                 const float* __restrict__ gW3, const float* __restrict__ gb3,
                 float* __restrict__ out, int ntiles)
{
    const int tid = threadIdx.x;

    conv_w<1>(gW1,  80, 256, sm + OW1, tid);
    conv_w<2>(gW2, 256, 256, sm + OW2, tid);
    conv_w<3>(gW3, 256,  64, sm + OW3, tid);
    for (int i = tid; i < 256; i += NT) {
        ((float*)(sm + OB1))[i] = gb1[i];
        ((float*)(sm + OB2))[i] = gb2[i];
    }
    for (int i = tid; i < 64; i += NT) ((float*)(sm + OB3))[i] = gb3[i];
    __syncthreads();

    const float* B1 = (const float*)(sm + OB1);
    const float* B2 = (const float*)(sm + OB2);
    const float* B3 = (const float*)(sm + OB3);

    const int w  = tid >> 5, l = tid & 31;
    const int m0 = w * 16;
    const int rl = l >> 2;
    const int cp = (l & 3) * 2;

    for (int tile = blockIdx.x; tile < ntiles; tile += GRID) {
        const long rowlo = (long)tile * 128 + m0 + rl;
        const float* obs_lo = obs + rowlo * 64;
        const float* obs_hi = obs_lo + 8 * 64;
        uint32_t* kt = g_k + ((size_t)tile * 5) * 16 * NT + tid;

        // A-frags: ks 0..3 = x (rebuilt per stage), ks 4 = actions (persistent)
        uint32_t xa[5][4];
        {
            const float* act_lo = act + rowlo * 16;
            float2 v;
            v = *(const float2*)(act_lo + cp);           xa[4][0] = packh(v.x, v.y);
            v = *(const float2*)(act_lo + 128 + cp);     xa[4][1] = packh(v.x, v.y);
            v = *(const float2*)(act_lo + 8 + cp);       xa[4][2] = packh(v.x, v.y);
            v = *(const float2*)(act_lo + 128 + 8 + cp); xa[4][3] = packh(v.x, v.y);
        }

        #pragma unroll 1   // one body copy: no spills, small I$
        for (int st = 0; st < 6; st++) {
            // ---- build x_st A-frags: fp32 y0 (L2-hot) + dt * sum_j a[st][j]*k_j ----
            #pragma unroll
            for (int ks = 0; ks < 4; ks++)
                #pragma unroll
                for (int r = 0; r < 4; r++) {
                    const int q = ks * 4 + r;
                    const float* yp = ((r & 1) ? obs_hi : obs_lo) + ks * 16 + (r >> 1) * 8 + cp;
                    float2 v = *(const float2*)yp;
                    #pragma unroll
                    for (int j = 0; j < 5; j++)
                        if (j < st) {
                            float a = DTf * c_A[st][j];
                            float2 kk = unpackh(kt[(j * 16 + q) * NT]);
                            v.x = fmaf(a, kk.x, v.x);
                            v.y = fmaf(a, kk.y, v.y);
                        }
                    xa[ks][r] = packh(v.x, v.y);
                }

            // ---- GEMM1: h1 = silu(X @ W1 + b1), f16 acc -> hA frags ----
            uint32_t hA[16][4];
            #pragma unroll
            for (int c = 0; c < 4; c++) {
                const uint4* q1 = (const uint4*)(sm + OW1 + c * 10240) + l;
                const uint2* s1 = (const uint2*)(sm + OW1 + c * 10240 + 8192) + l;
                uint32_t acc[8][2];
                #pragma unroll
                for (int nf = 0; nf < 8; nf++) {
                    float2 bb = *(const float2*)(B1 + c * 64 + nf * 8 + cp);
                    uint32_t bh = packh(bb.x, bb.y);
                    acc[nf][0] = bh; acc[nf][1] = bh;
                }
                #pragma unroll
                for (int p = 0; p < 2; p++)
                    #pragma unroll
                    for (int nf = 0; nf < 8; nf++) {
                        uint4 bb = q1[(p * 8 + nf) * 32];
                        mma_f16h(acc[nf], xa[2 * p],     bb.x, bb.y);
                        mma_f16h(acc[nf], xa[2 * p + 1], bb.z, bb.w);
                    }
                #pragma unroll
                for (int nf = 0; nf < 8; nf++) {
                    uint2 bb = s1[nf * 32];
                    mma_f16h(acc[nf], xa[4], bb.x, bb.y);
                }
                #pragma unroll
                for (int nf = 0; nf < 8; nf++) {
                    float2 v0 = unpackh(acc[nf][0]);
                    float2 v1 = unpackh(acc[nf][1]);
                    hA[c * 4 + (nf >> 1)][(nf & 1) * 2 + 0] = packh(silu(v0.x), silu(v0.y));
                    hA[c * 4 + (nf >> 1)][(nf & 1) * 2 + 1] = packh(silu(v1.x), silu(v1.y));
                }
            }

            // ---- GEMM2 (f16 acc, silu) + fused GEMM3 partials (f16 acc, bias-seeded) ----
            uint32_t acc3[8][2];
            #pragma unroll
            for (int nf = 0; nf < 8; nf++) {
                float2 bb = *(const float2*)(B3 + nf * 8 + cp);
                uint32_t bh = packh(bb.x, bb.y);
                acc3[nf][0] = bh; acc3[nf][1] = bh;   // k = b3 + sum (f16 acc)
            }

            #pragma unroll 1
            for (int c = 0; c < 4; c++) {
                const uint4* q2 = (const uint4*)(sm + OW2 + c * 32768) + l;
                const uint4* q3 = (const uint4*)(sm + OW3 + c * 8192) + l;
                uint32_t acc[8][2];
                #pragma unroll
                for (int nf = 0; nf < 8; nf++) {
                    float2 bb = *(const float2*)(B2 + c * 64 + nf * 8 + cp);
                    uint32_t bh = packh(bb.x, bb.y);
                    acc[nf][0] = bh; acc[nf][1] = bh;
                }
                #pragma unroll
                for (int p = 0; p < 8; p++)
                    #pragma unroll
                    for (int nf = 0; nf < 8; nf++) {
                        uint4 bb = q2[(p * 8 + nf) * 32];
                        mma_f16h(acc[nf], hA[2 * p],     bb.x, bb.y);
                        mma_f16h(acc[nf], hA[2 * p + 1], bb.z, bb.w);
                    }
                uint32_t ht[4][4];
                #pragma unroll
                for (int nf = 0; nf < 8; nf++) {
                    float2 v0 = unpackh(acc[nf][0]);
                    float2 v1 = unpackh(acc[nf][1]);
                    ht[nf >> 1][(nf & 1) * 2 + 0] = packh(silu(v0.x), silu(v0.y));
                    ht[nf >> 1][(nf & 1) * 2 + 1] = packh(silu(v1.x), silu(v1.y));
                }
                #pragma unroll
                for (int jp = 0; jp < 2; jp++)
                    #pragma unroll
                    for (int nf = 0; nf < 8; nf++) {
                        uint4 bb = q3[(jp * 8 + nf) * 32];
                        mma_f16h(acc3[nf], ht[2 * jp],     bb.x, bb.y);
                        mma_f16h(acc3[nf], ht[2 * jp + 1], bb.z, bb.w);
                    }
            }

            // ---- GEMM3 epilogue: k_st = acc3 (bias already inside) ----
            if (st < 5) {
                #pragma unroll
                for (int nf = 0; nf < 8; nf++) {
                    int q = (nf >> 1) * 4 + (nf & 1) * 2;
                    kt[(st * 16 + q + 0) * NT] = acc3[nf][0];   // direct f16x2 store
                    kt[(st * 16 + q + 1) * NT] = acc3[nf][1];
                }
            } else {
                float* o_lo = out + rowlo * 64;
                float* o_hi = o_lo + 8 * 64;
                const float d5 = DTf * c_Bc[5];
                #pragma unroll
                for (int nf = 0; nf < 8; nf++) {
                    float2 ylo = *(const float2*)(obs_lo + nf * 8 + cp);
                    float2 yhi = *(const float2*)(obs_hi + nf * 8 + cp);
                    float2 k5lo = unpackh(acc3[nf][0]);
                    float2 k5hi = unpackh(acc3[nf][1]);
                    float lo0 = fmaf(d5, k5lo.x, ylo.x);
                    float lo1 = fmaf(d5, k5lo.y, ylo.y);
                    float hi0 = fmaf(d5, k5hi.x, yhi.x);
                    float hi1 = fmaf(d5, k5hi.y, yhi.y);
                    int ql = (nf >> 1) * 4 + (nf & 1) * 2, qh = ql + 1;
                    #pragma unroll
                    for (int j = 0; j < 5; j++) {
                        float d = DTf * c_Bc[j];
                        float2 klo = unpackh(kt[(j * 16 + ql) * NT]);
                        float2 khi = unpackh(kt[(j * 16 + qh) * NT]);
                        lo0 = fmaf(d, klo.x, lo0); lo1 = fmaf(d, klo.y, lo1);
                        hi0 = fmaf(d, khi.x, hi0); hi1 = fmaf(d, khi.y, hi1);
                    }
                    *(float2*)(o_lo + nf * 8 + cp) = make_float2(lo0, lo1);
                    *(float2*)(o_hi + nf * 8 + cp) = make_float2(hi0, hi1);
                }
            }
        }
    }
}

extern "C" void kernel_launch(void* const* d_in, const int* in_sizes, int n_in,
                              void* d_out, int out_size)
{
    const float* obs = (const float*)d_in[0];
    const float* act = (const float*)d_in[1];
    const float* W1  = (const float*)d_in[2];
    const float* b1  = (const float*)d_in[3];
    const float* W2  = (const float*)d_in[4];
    const float* b2  = (const float*)d_in[5];
    const float* W3  = (const float*)d_in[6];
    const float* b3  = (const float*)d_in[7];
    float* out = (float*)d_out;

    const int batch  = in_sizes[0] / 64;
    int ntiles = batch / 128;
    if (ntiles > MAXTILES) ntiles = MAXTILES;

    cudaFuncSetAttribute(tsit5_mma_kernel,
                         cudaFuncAttributeMaxDynamicSharedMemorySize, SMEM_BYTES);

    tsit5_mma_kernel<<<GRID, NT, SMEM_BYTES>>>(obs, act, W1, b1, W2, b2, W3, b3, out, ntiles);
}

// round 13
// speedup vs baseline: 1.0179x; 1.0093x over previous
#include <cuda_runtime.h>
#include <cuda_fp16.h>
#include <cstdint>

#define NT    256
#define GRID  148
#define DTf   0.05f
#define MAXTILES 1024

// ---------------- Tsit5 tableau ----------------
__constant__ float c_A[6][5] = {
    {0.f, 0.f, 0.f, 0.f, 0.f},
    {0.161f, 0.f, 0.f, 0.f, 0.f},
    {-0.008480655492356989f, 0.335480655492357f, 0.f, 0.f, 0.f},
    {2.8971530571054935f, -6.359448489975075f, 4.3622954328695815f, 0.f, 0.f},
    {5.325864828439257f, -11.748883564062828f, 7.4955393428898365f, -0.09249506636175525f, 0.f},
    {5.86145544294642f, -12.92096931784711f, 8.159367898576159f, -0.071584973281401f, -0.028269050394068383f},
};
__constant__ float c_Bc[6] = {
    0.09646076681806523f, 0.01f, 0.4798896504144996f,
    1.379008574103742f, -3.290069515436081f, 2.324710524099774f
};

// k_1..k_5 stage derivatives, f16x2 fragments, [tile][stage][q][tid] (coalesced on tid).
__device__ uint32_t g_k[(size_t)MAXTILES * 5 * 16 * NT];

// ---------------- SMEM layout (bytes) ----------------
// B-fragments PAIRED (two consecutive-ks frags adjacent, 16B/lane -> LDS.128).
//  W1 per c1 (10240B): pair p(2)*nf(8)*512B, then single ks4: nf(8)*256B
//  W2 per nc (32768B): (kp*8+nf)*512B, kp = global k-pair 0..7
//  W3 per nc (8192B):  (jp*8+nf)*512B
#define OW1 0          // 4 * 10240 = 40960
#define OW2 40960      // 4 * 32768 = 131072
#define OW3 172032     // 4 * 8192  = 32768
#define OB1 204800     // 256 f32
#define OB2 205824     // 256 f32
#define OB3 206848     // 64 f32
#define SMEM_BYTES 207360

// ---------------- helpers ----------------
__device__ __forceinline__ uint32_t packh(float lo, float hi) {
    uint32_t r; asm("cvt.rn.f16x2.f32 %0, %1, %2;" : "=r"(r) : "f"(hi), "f"(lo)); return r;
}
__device__ __forceinline__ float2 unpackh(uint32_t v) {
    __half2 h = *reinterpret_cast<__half2*>(&v);
    return __half22float2(h);
}
__device__ __forceinline__ float tanh_fast(float x) {
    float y; asm("tanh.approx.f32 %0, %1;" : "=f"(y) : "f"(x)); return y;
}
__device__ __forceinline__ float silu(float x) {
    float t = tanh_fast(0.5f * x);
    return fmaf(x, 0.5f * t, 0.5f * x);
}
// f16 inputs, f16 accumulate (C/D = 2 regs)
__device__ __forceinline__ void mma_f16h(uint32_t* c, const uint32_t* a, uint32_t b0, uint32_t b1) {
    asm volatile(
        "mma.sync.aligned.m16n8k16.row.col.f16.f16.f16.f16 "
        "{%0,%1},{%2,%3,%4,%5},{%6,%7},{%0,%1};"
        : "+r"(c[0]), "+r"(c[1])
        : "r"(a[0]), "r"(a[1]), "r"(a[2]), "r"(a[3]), "r"(b0), "r"(b1));
}

// W[K][N] row-major f32 -> f16 paired B-fragment SMEM (layouts above).
template<int MODE>
__device__ void conv_w(const float* __restrict__ G, int K, int N, char* dst, int tid) {
    for (int idx = tid; idx < K * N; idx += NT) {
        int k = idx / N, n = idx - k * N;
        int lane = (n & 7) * 4 + ((k & 7) >> 1);
        int kb = (((k >> 3) & 1) << 2) + ((k & 1) << 1);   // byte offset within 8B frag
        int ks = k >> 4;
        int off;
        if (MODE == 1) {
            int c = n >> 6, nf = (n >> 3) & 7;
            if (ks < 4)
                off = c * 10240 + (ks >> 1) * 4096 + nf * 512 + lane * 16 + (ks & 1) * 8 + kb;
            else
                off = c * 10240 + 8192 + nf * 256 + lane * 8 + kb;
        } else if (MODE == 2) {
            int c = n >> 6, nf = (n >> 3) & 7;
            off = c * 32768 + ((ks >> 1) * 8 + nf) * 512 + lane * 16 + (ks & 1) * 8 + kb;
        } else {
            int nf = n >> 3, c = ks >> 2, jp = (ks >> 1) & 1;
            off = c * 8192 + (jp * 8 + nf) * 512 + lane * 16 + (ks & 1) * 8 + kb;
        }
        *(__half*)(dst + off) = __float2half(G[idx]);
    }
}

extern __shared__ char sm[];

__global__ void __launch_bounds__(NT, 1)
tsit5_mma_kernel(const float* __restrict__ obs, const float* __restrict__ act,
                 const float* __restrict__ gW1, const float* __restrict__ gb1,
                 const float* __restrict__ gW2, const float* __restrict__ gb2,
                 const float* __restrict__ gW3, const float* __restrict__ gb3,
                 float* __restrict__ out, int ntiles)
{
    const int tid = threadIdx.x;

    conv_w<1>(gW1,  80, 256, sm + OW1, tid);
    conv_w<2>(gW2, 256, 256, sm + OW2, tid);
    conv_w<3>(gW3, 256,  64, sm + OW3, tid);
    for (int i = tid; i < 256; i += NT) {
        ((float*)(sm + OB1))[i] = gb1[i];
        ((float*)(sm + OB2))[i] = gb2[i];
    }
    for (int i = tid; i < 64; i += NT) ((float*)(sm + OB3))[i] = gb3[i];
    __syncthreads();

    const float* B1 = (const float*)(sm + OB1);
    const float* B2 = (const float*)(sm + OB2);
    const float* B3 = (const float*)(sm + OB3);

    const int w  = tid >> 5, l = tid & 31;
    const int m0 = w * 16;
    const int rl = l >> 2;
    const int cp = (l & 3) * 2;

    for (int tile = blockIdx.x; tile < ntiles; tile += GRID) {
        const long rowlo = (long)tile * 128 + m0 + rl;
        const float* obs_lo = obs + rowlo * 64;
        const float* obs_hi = obs_lo + 8 * 64;
        uint32_t* kt = g_k + ((size_t)tile * 5) * 16 * NT + tid;

        // A-frags: ks 0..3 = x (rebuilt per stage), ks 4 = actions (persistent)
        uint32_t xa[5][4];
        {
            const float* act_lo = act + rowlo * 16;
            float2 v;
            v = *(const float2*)(act_lo + cp);           xa[4][0] = packh(v.x, v.y);
            v = *(const float2*)(act_lo + 128 + cp);     xa[4][1] = packh(v.x, v.y);
            v = *(const float2*)(act_lo + 8 + cp);       xa[4][2] = packh(v.x, v.y);
            v = *(const float2*)(act_lo + 128 + 8 + cp); xa[4][3] = packh(v.x, v.y);
        }

        #pragma unroll 1   // one body copy: no spills, small I$
        for (int st = 0; st < 6; st++) {
            // ---- build x_st A-frags: fp32 y0 (L2-hot) + dt * sum_j a[st][j]*k_j ----
            #pragma unroll
            for (int ks = 0; ks < 4; ks++)
                #pragma unroll
                for (int r = 0; r < 4; r++) {
                    const int q = ks * 4 + r;
                    const float* yp = ((r & 1) ? obs_hi : obs_lo) + ks * 16 + (r >> 1) * 8 + cp;
                    float2 v = *(const float2*)yp;
                    #pragma unroll
                    for (int j = 0; j < 5; j++)
                        if (j < st) {
                            float a = DTf * c_A[st][j];
                            float2 kk = unpackh(kt[(j * 16 + q) * NT]);
                            v.x = fmaf(a, kk.x, v.x);
                            v.y = fmaf(a, kk.y, v.y);
                        }
                    xa[ks][r] = packh(v.x, v.y);
                }

            // ---- all-N GEMM2 accumulators, bias-seeded ----
            uint32_t acc2[32][2];
            #pragma unroll
            for (int nc = 0; nc < 4; nc++)
                #pragma unroll
                for (int nf = 0; nf < 8; nf++) {
                    float2 bb = *(const float2*)(B2 + nc * 64 + nf * 8 + cp);
                    uint32_t bh = packh(bb.x, bb.y);
                    acc2[nc * 8 + nf][0] = bh; acc2[nc * 8 + nf][1] = bh;
                }

            // ---- streamed pipeline: per chunk c1, GEMM1 N-chunk -> silu -> GEMM2 K-partial ----
            #pragma unroll
            for (int c1 = 0; c1 < 4; c1++) {
                const uint4* q1 = (const uint4*)(sm + OW1 + c1 * 10240) + l;
                const uint2* s1 = (const uint2*)(sm + OW1 + c1 * 10240 + 8192) + l;
                uint32_t acc1[8][2];
                #pragma unroll
                for (int nf = 0; nf < 8; nf++) {
                    float2 bb = *(const float2*)(B1 + c1 * 64 + nf * 8 + cp);
                    uint32_t bh = packh(bb.x, bb.y);
                    acc1[nf][0] = bh; acc1[nf][1] = bh;
                }
                #pragma unroll
                for (int p = 0; p < 2; p++)
                    #pragma unroll
                    for (int nf = 0; nf < 8; nf++) {
                        uint4 bb = q1[(p * 8 + nf) * 32];
                        mma_f16h(acc1[nf], xa[2 * p],     bb.x, bb.y);
                        mma_f16h(acc1[nf], xa[2 * p + 1], bb.z, bb.w);
                    }
                #pragma unroll
                for (int nf = 0; nf < 8; nf++) {
                    uint2 bb = s1[nf * 32];
                    mma_f16h(acc1[nf], xa[4], bb.x, bb.y);
                }
                // silu -> transient h1 chunk (4 ksteps of GEMM2's K)
                uint32_t ht[4][4];
                #pragma unroll
                for (int nf = 0; nf < 8; nf++) {
                    float2 v0 = unpackh(acc1[nf][0]);
                    float2 v1 = unpackh(acc1[nf][1]);
                    ht[nf >> 1][(nf & 1) * 2 + 0] = packh(silu(v0.x), silu(v0.y));
                    ht[nf >> 1][(nf & 1) * 2 + 1] = packh(silu(v1.x), silu(v1.y));
                }
                // GEMM2 K-partial: global k-pairs 2*c1, 2*c1+1 across ALL N
                #pragma unroll
                for (int p = 0; p < 2; p++)
                    #pragma unroll
                    for (int nc = 0; nc < 4; nc++) {
                        const uint4* q2 = (const uint4*)(sm + OW2 + nc * 32768) + l;
                        #pragma unroll
                        for (int nf = 0; nf < 8; nf++) {
                            uint4 bb = q2[((2 * c1 + p) * 8 + nf) * 32];
                            mma_f16h(acc2[nc * 8 + nf], ht[2 * p],     bb.x, bb.y);
                            mma_f16h(acc2[nc * 8 + nf], ht[2 * p + 1], bb.z, bb.w);
                        }
                    }
            }

            // ---- GEMM2 epilogue + streamed GEMM3 (bias-seeded f16 acc) ----
            uint32_t acc3[8][2];
            #pragma unroll
            for (int nf = 0; nf < 8; nf++) {
                float2 bb = *(const float2*)(B3 + nf * 8 + cp);
                uint32_t bh = packh(bb.x, bb.y);
                acc3[nf][0] = bh; acc3[nf][1] = bh;
            }
            #pragma unroll
            for (int nc = 0; nc < 4; nc++) {
                const uint4* q3 = (const uint4*)(sm + OW3 + nc * 8192) + l;
                uint32_t ht2[4][4];
                #pragma unroll
                for (int nf = 0; nf < 8; nf++) {
                    float2 v0 = unpackh(acc2[nc * 8 + nf][0]);
                    float2 v1 = unpackh(acc2[nc * 8 + nf][1]);
                    ht2[nf >> 1][(nf & 1) * 2 + 0] = packh(silu(v0.x), silu(v0.y));
                    ht2[nf >> 1][(nf & 1) * 2 + 1] = packh(silu(v1.x), silu(v1.y));
                }
                #pragma unroll
                for (int jp = 0; jp < 2; jp++)
                    #pragma unroll
                    for (int nf = 0; nf < 8; nf++) {
                        uint4 bb = q3[(jp * 8 + nf) * 32];
                        mma_f16h(acc3[nf], ht2[2 * jp],     bb.x, bb.y);
                        mma_f16h(acc3[nf], ht2[2 * jp + 1], bb.z, bb.w);
                    }
            }

            // ---- k epilogue: k_st = acc3 (bias inside) ----
            if (st < 5) {
                #pragma unroll
                for (int nf = 0; nf < 8; nf++) {
                    int q = (nf >> 1) * 4 + (nf & 1) * 2;
                    kt[(st * 16 + q + 0) * NT] = acc3[nf][0];
                    kt[(st * 16 + q + 1) * NT] = acc3[nf][1];
                }
            } else {
                float* o_lo = out + rowlo * 64;
                float* o_hi = o_lo + 8 * 64;
                const float d5 = DTf * c_Bc[5];
                #pragma unroll
                for (int nf = 0; nf < 8; nf++) {
                    float2 ylo = *(const float2*)(obs_lo + nf * 8 + cp);
                    float2 yhi = *(const float2*)(obs_hi + nf * 8 + cp);
                    float2 k5lo = unpackh(acc3[nf][0]);
                    float2 k5hi = unpackh(acc3[nf][1]);
                    float lo0 = fmaf(d5, k5lo.x, ylo.x);
                    float lo1 = fmaf(d5, k5lo.y, ylo.y);
                    float hi0 = fmaf(d5, k5hi.x, yhi.x);
                    float hi1 = fmaf(d5, k5hi.y, yhi.y);
                    int ql = (nf >> 1) * 4 + (nf & 1) * 2, qh = ql + 1;
                    #pragma unroll
                    for (int j = 0; j < 5; j++) {
                        float d = DTf * c_Bc[j];
                        float2 klo = unpackh(kt[(j * 16 + ql) * NT]);
                        float2 khi = unpackh(kt[(j * 16 + qh) * NT]);
                        lo0 = fmaf(d, klo.x, lo0); lo1 = fmaf(d, klo.y, lo1);
                        hi0 = fmaf(d, khi.x, hi0); hi1 = fmaf(d, khi.y, hi1);
                    }
                    *(float2*)(o_lo + nf * 8 + cp) = make_float2(lo0, lo1);
                    *(float2*)(o_hi + nf * 8 + cp) = make_float2(hi0, hi1);
                }
            }
        }
    }
}

extern "C" void kernel_launch(void* const* d_in, const int* in_sizes, int n_in,
                              void* d_out, int out_size)
{
    const float* obs = (const float*)d_in[0];
    const float* act = (const float*)d_in[1];
    const float* W1  = (const float*)d_in[2];
    const float* b1  = (const float*)d_in[3];
    const float* W2  = (const float*)d_in[4];
    const float* b2  = (const float*)d_in[5];
    const float* W3  = (const float*)d_in[6];
    const float* b3  = (const float*)d_in[7];
    float* out = (float*)d_out;

    const int batch  = in_sizes[0] / 64;
    int ntiles = batch / 128;
    if (ntiles > MAXTILES) ntiles = MAXTILES;

    cudaFuncSetAttribute(tsit5_mma_kernel,
                         cudaFuncAttributeMaxDynamicSharedMemorySize, SMEM_BYTES);

    tsit5_mma_kernel<<<GRID, NT, SMEM_BYTES>>>(obs, act, W1, b1, W2, b2, W3, b3, out, ntiles);
}